// round 3
// baseline (speedup 1.0000x reference)
#include <cuda_runtime.h>
#include <math.h>

#define BB 2
#define TT 2048
#define DD 1024
#define HH 16
#define HDIM 64
#define MROWS (BB * TT)   // 4096

typedef unsigned long long u64;

// Scratch (static device globals -- no allocation in kernel_launch)
__device__ float g_qkv[(size_t)MROWS * 3 * DD];   // [4096, 3072]
__device__ float g_yatt[(size_t)MROWS * DD];      // [4096, 1024]

// ---------------------------------------------------------------------------
// packed fp32x2 helpers (Blackwell FFMA2 -- 2x fp32 FMA throughput)
// ---------------------------------------------------------------------------
__device__ __forceinline__ u64 pack2(float x, float y) {
    u64 r;
    asm("mov.b64 %0, {%1, %2};" : "=l"(r) : "f"(x), "f"(y));
    return r;
}
__device__ __forceinline__ void unpack2(u64 v, float& x, float& y) {
    asm("mov.b64 {%0, %1}, %2;" : "=f"(x), "=f"(y) : "l"(v));
}
__device__ __forceinline__ void ffma2(u64& d, u64 a, u64 b) {
    asm("fma.rn.f32x2 %0, %1, %2, %0;" : "+l"(d) : "l"(a), "l"(b));
}

// ---------------------------------------------------------------------------
// SGEMM: C[m,n] = sum_k A[m,k]*W[n,k] + bias[n]
// 128x128x16 tiles, 256 threads, 8x8 microtile, double-buffered smem, FFMA2.
// M,N multiples of 128; K multiple of 16.
// ---------------------------------------------------------------------------
__device__ __forceinline__ void gemm128_body(const float* __restrict__ A,
                                             const float* __restrict__ W,
                                             const float* __restrict__ bias,
                                             float* __restrict__ C,
                                             int N, int K) {
    __shared__ __align__(16) float As[2][16][132];
    __shared__ __align__(16) float Ws[2][16][132];

    const int tid = threadIdx.x;
    const int tx = tid & 15;          // n microtile
    const int ty = tid >> 4;          // m microtile
    const int m0 = blockIdx.y * 128;
    const int n0 = blockIdx.x * 128;

    const int row = tid >> 2;         // 0..63 (loader row; +64 for second half)
    const int sg  = (tid & 3) * 4;    // k segment 0,4,8,12

    const float* Ap = A + (size_t)(m0 + row) * K + sg;
    const float* Wp = W + (size_t)(n0 + row) * K + sg;
    const size_t half = (size_t)64 * K;

    u64 acc[8][4];
    #pragma unroll
    for (int i = 0; i < 8; i++)
        #pragma unroll
        for (int j = 0; j < 4; j++) acc[i][j] = 0ull;

    // prologue: load stage 0
    float4 a0v = *(const float4*)(Ap);
    float4 a1v = *(const float4*)(Ap + half);
    float4 w0v = *(const float4*)(Wp);
    float4 w1v = *(const float4*)(Wp + half);

    As[0][sg + 0][row] = a0v.x; As[0][sg + 1][row] = a0v.y;
    As[0][sg + 2][row] = a0v.z; As[0][sg + 3][row] = a0v.w;
    As[0][sg + 0][row + 64] = a1v.x; As[0][sg + 1][row + 64] = a1v.y;
    As[0][sg + 2][row + 64] = a1v.z; As[0][sg + 3][row + 64] = a1v.w;
    Ws[0][sg + 0][row] = w0v.x; Ws[0][sg + 1][row] = w0v.y;
    Ws[0][sg + 2][row] = w0v.z; Ws[0][sg + 3][row] = w0v.w;
    Ws[0][sg + 0][row + 64] = w1v.x; Ws[0][sg + 1][row + 64] = w1v.y;
    Ws[0][sg + 2][row + 64] = w1v.z; Ws[0][sg + 3][row + 64] = w1v.w;
    __syncthreads();

    const int NT = K / 16;
    int buf = 0;
    for (int kt = 0; kt < NT; kt++) {
        if (kt + 1 < NT) {
            const float* Ap2 = Ap + (kt + 1) * 16;
            const float* Wp2 = Wp + (kt + 1) * 16;
            a0v = *(const float4*)(Ap2);
            a1v = *(const float4*)(Ap2 + half);
            w0v = *(const float4*)(Wp2);
            w1v = *(const float4*)(Wp2 + half);
        }

        #pragma unroll
        for (int kk = 0; kk < 16; kk++) {
            float4 a_lo = *(const float4*)&As[buf][kk][ty * 4];
            float4 a_hi = *(const float4*)&As[buf][kk][64 + ty * 4];
            u64 b0 = *(const u64*)&Ws[buf][kk][tx * 4];
            u64 b1 = *(const u64*)&Ws[buf][kk][tx * 4 + 2];
            u64 b2 = *(const u64*)&Ws[buf][kk][64 + tx * 4];
            u64 b3 = *(const u64*)&Ws[buf][kk][64 + tx * 4 + 2];
            float av[8] = {a_lo.x, a_lo.y, a_lo.z, a_lo.w,
                           a_hi.x, a_hi.y, a_hi.z, a_hi.w};
            #pragma unroll
            for (int i = 0; i < 8; i++) {
                u64 ad = pack2(av[i], av[i]);
                ffma2(acc[i][0], ad, b0);
                ffma2(acc[i][1], ad, b1);
                ffma2(acc[i][2], ad, b2);
                ffma2(acc[i][3], ad, b3);
            }
        }

        if (kt + 1 < NT) {
            const int nb = buf ^ 1;
            As[nb][sg + 0][row] = a0v.x; As[nb][sg + 1][row] = a0v.y;
            As[nb][sg + 2][row] = a0v.z; As[nb][sg + 3][row] = a0v.w;
            As[nb][sg + 0][row + 64] = a1v.x; As[nb][sg + 1][row + 64] = a1v.y;
            As[nb][sg + 2][row + 64] = a1v.z; As[nb][sg + 3][row + 64] = a1v.w;
            Ws[nb][sg + 0][row] = w0v.x; Ws[nb][sg + 1][row] = w0v.y;
            Ws[nb][sg + 2][row] = w0v.z; Ws[nb][sg + 3][row] = w0v.w;
            Ws[nb][sg + 0][row + 64] = w1v.x; Ws[nb][sg + 1][row + 64] = w1v.y;
            Ws[nb][sg + 2][row + 64] = w1v.z; Ws[nb][sg + 3][row + 64] = w1v.w;
        }
        __syncthreads();
        buf ^= 1;
    }

    // epilogue: unpack, add bias, store
    float4 bv0 = *(const float4*)(bias + n0 + tx * 4);
    float4 bv1 = *(const float4*)(bias + n0 + 64 + tx * 4);
    #pragma unroll
    for (int i = 0; i < 8; i++) {
        const int m = m0 + ((i < 4) ? (ty * 4 + i) : (64 + ty * 4 + i - 4));
        float4 r0, r1;
        unpack2(acc[i][0], r0.x, r0.y);
        unpack2(acc[i][1], r0.z, r0.w);
        unpack2(acc[i][2], r1.x, r1.y);
        unpack2(acc[i][3], r1.z, r1.w);
        r0.x += bv0.x; r0.y += bv0.y; r0.z += bv0.z; r0.w += bv0.w;
        r1.x += bv1.x; r1.y += bv1.y; r1.z += bv1.z; r1.w += bv1.w;
        *(float4*)(C + (size_t)m * N + n0 + tx * 4) = r0;
        *(float4*)(C + (size_t)m * N + n0 + 64 + tx * 4) = r1;
    }
}

__global__ __launch_bounds__(256) void qkv_gemm_kernel(const float* __restrict__ x,
                                                       const float* __restrict__ w_qkv,
                                                       const float* __restrict__ b_qkv) {
    gemm128_body(x, w_qkv, b_qkv, g_qkv, 3 * DD, DD);
}

__global__ __launch_bounds__(256) void proj_gemm_kernel(const float* __restrict__ w_proj,
                                                        const float* __restrict__ b_proj,
                                                        float* __restrict__ out) {
    gemm128_body(g_yatt, w_proj, b_proj, out, DD, DD);
}

// ---------------------------------------------------------------------------
// Flash attention (fp32, causal). One block = (q-tile of 64, head, batch).
// 8 warps; warp w owns query rows w*8..w*8+7. Scores/outputs in registers,
// P staged in warp-private smem region for the PV accumulation.
// ---------------------------------------------------------------------------
__global__ __launch_bounds__(256) void flash_attn_kernel() {
    const int qt = blockIdx.x;
    const int h  = blockIdx.y;
    const int b  = blockIdx.z;

    extern __shared__ __align__(16) float sm[];
    float (*Qs)[64] = (float(*)[64])(sm);
    float (*Ks)[64] = (float(*)[64])(sm + 64 * 64);       // swizzled [r][d ^ (r&31)]
    float (*Vs)[64] = (float(*)[64])(sm + 2 * 64 * 64);
    float (*Ps)[64] = (float(*)[64])(sm + 3 * 64 * 64);   // warp-private rows

    const int tid  = threadIdx.x;
    const int warp = tid >> 5;
    const int lane = tid & 31;
    const int r_base = warp * 8;
    const int q0 = qt * 64;
    const float scale = 0.125f;

    for (int i = tid; i < 64 * 64; i += 256) {
        int r = i >> 6, d = i & 63;
        Qs[r][d] = g_qkv[((size_t)(b * TT + q0 + r)) * (3 * DD) + h * HDIM + d] * scale;
    }

    float m[8], l[8], o0[8], o1[8];
    #pragma unroll
    for (int rr = 0; rr < 8; rr++) {
        m[rr] = -3.0e38f; l[rr] = 0.f; o0[rr] = 0.f; o1[rr] = 0.f;
    }

    for (int kt = 0; kt <= qt; kt++) {
        const int k0 = kt * 64;
        __syncthreads();   // Q/prev-P consumed; safe to overwrite K/V
        for (int i = tid; i < 64 * 64; i += 256) {
            int r = i >> 6, d = i & 63;
            size_t base = ((size_t)(b * TT + k0 + r)) * (3 * DD) + h * HDIM + d;
            Ks[r][d ^ (r & 31)] = g_qkv[base + DD];
            Vs[r][d]            = g_qkv[base + 2 * DD];
        }
        __syncthreads();

        // ---- S = Q K^T (per-warp 8x64 tile in registers) ----
        float s0[8], s1[8];
        #pragma unroll
        for (int rr = 0; rr < 8; rr++) { s0[rr] = 0.f; s1[rr] = 0.f; }

        #pragma unroll 4
        for (int d4 = 0; d4 < 64; d4 += 4) {
            float ka[4], kb[4];
            #pragma unroll
            for (int j = 0; j < 4; j++) {
                ka[j] = Ks[lane][(d4 + j) ^ lane];
                kb[j] = Ks[lane + 32][(d4 + j) ^ lane];
            }
            #pragma unroll
            for (int rr = 0; rr < 8; rr++) {
                float4 qv = *(const float4*)&Qs[r_base + rr][d4];
                s0[rr] = fmaf(qv.x, ka[0], fmaf(qv.y, ka[1],
                         fmaf(qv.z, ka[2], fmaf(qv.w, ka[3], s0[rr]))));
                s1[rr] = fmaf(qv.x, kb[0], fmaf(qv.y, kb[1],
                         fmaf(qv.z, kb[2], fmaf(qv.w, kb[3], s1[rr]))));
            }
        }

        // ---- online softmax + stage P ----
        const bool diag = (kt == qt);
        #pragma unroll
        for (int rr = 0; rr < 8; rr++) {
            const int r = r_base + rr;
            float v0 = s0[rr], v1 = s1[rr];
            if (diag) {
                const int qg = q0 + r;
                if (k0 + lane > qg)      v0 = -3.0e38f;
                if (k0 + lane + 32 > qg) v1 = -3.0e38f;
            }
            float rmax = fmaxf(v0, v1);
            #pragma unroll
            for (int off = 16; off; off >>= 1)
                rmax = fmaxf(rmax, __shfl_xor_sync(0xffffffffu, rmax, off));

            const float mnew = fmaxf(m[rr], rmax);
            const float corr = __expf(m[rr] - mnew);
            const float p0 = __expf(v0 - mnew);
            const float p1 = __expf(v1 - mnew);

            float rs = p0 + p1;
            #pragma unroll
            for (int off = 16; off; off >>= 1)
                rs += __shfl_xor_sync(0xffffffffu, rs, off);

            l[rr] = l[rr] * corr + rs;
            m[rr] = mnew;
            o0[rr] *= corr;
            o1[rr] *= corr;
            Ps[r][lane]      = p0;
            Ps[r][lane + 32] = p1;
        }
        __syncwarp();

        // ---- O += P V (per-warp, P from warp-private smem) ----
        #pragma unroll 4
        for (int c4 = 0; c4 < 64; c4 += 4) {
            float va[4], vb[4];
            #pragma unroll
            for (int j = 0; j < 4; j++) {
                va[j] = Vs[c4 + j][lane];
                vb[j] = Vs[c4 + j][lane + 32];
            }
            #pragma unroll
            for (int rr = 0; rr < 8; rr++) {
                float4 pv = *(const float4*)&Ps[r_base + rr][c4];
                o0[rr] = fmaf(pv.x, va[0], fmaf(pv.y, va[1],
                         fmaf(pv.z, va[2], fmaf(pv.w, va[3], o0[rr]))));
                o1[rr] = fmaf(pv.x, vb[0], fmaf(pv.y, vb[1],
                         fmaf(pv.z, vb[2], fmaf(pv.w, vb[3], o1[rr]))));
            }
        }
    }

    // normalize and write back in [B,T,D] layout
    #pragma unroll
    for (int rr = 0; rr < 8; rr++) {
        const int r = r_base + rr;
        const float inv = 1.0f / l[rr];
        size_t base = ((size_t)(b * TT + q0 + r)) * DD + h * HDIM;
        g_yatt[base + lane]      = o0[rr] * inv;
        g_yatt[base + lane + 32] = o1[rr] * inv;
    }
}

// ---------------------------------------------------------------------------
// Launch: QKV GEMM -> flash attention -> output projection
// Inputs (metadata order): x, attn_mask(ignored; causal static),
//                          w_qkv, b_qkv, w_proj, b_proj
// ---------------------------------------------------------------------------
extern "C" void kernel_launch(void* const* d_in, const int* in_sizes, int n_in,
                              void* d_out, int out_size) {
    const float* x      = (const float*)d_in[0];
    const float* w_qkv  = (const float*)d_in[2];
    const float* b_qkv  = (const float*)d_in[3];
    const float* w_proj = (const float*)d_in[4];
    const float* b_proj = (const float*)d_in[5];
    float* out = (float*)d_out;

    // QKV projection: [4096,1024] x [3072,1024]^T -> g_qkv [4096,3072]
    {
        dim3 grid((3 * DD) / 128, MROWS / 128);
        qkv_gemm_kernel<<<grid, 256>>>(x, w_qkv, b_qkv);
    }

    // Flash attention: g_qkv -> g_yatt [4096,1024]
    {
        static int smem_set = 0;
        if (!smem_set) {
            cudaFuncSetAttribute(flash_attn_kernel,
                                 cudaFuncAttributeMaxDynamicSharedMemorySize, 65536);
            smem_set = 1;
        }
        dim3 grid(TT / 64, HH, BB);
        flash_attn_kernel<<<grid, 256, 65536>>>();
    }

    // Output projection: [4096,1024] x [1024,1024]^T -> out
    {
        dim3 grid(DD / 128, MROWS / 128);
        proj_gemm_kernel<<<grid, 256>>>(w_proj, b_proj, out);
    }
}

// round 6
// speedup vs baseline: 1.1505x; 1.1505x over previous
#include <cuda_runtime.h>
#include <cuda_bf16.h>
#include <cstdint>
#include <math.h>

#define BB 2
#define TT 2048
#define DD 1024
#define HH 16
#define HDIM 64
#define MROWS (BB * TT)   // 4096

typedef unsigned long long u64;

// ---------------------------------------------------------------------------
// Scratch (device globals; no allocation anywhere)
// ---------------------------------------------------------------------------
__device__ float g_qkv[(size_t)MROWS * 3 * DD];    // [4096, 3072] fp32
__device__ float g_yatt[(size_t)MROWS * DD];       // [4096, 1024] fp32

__device__ __align__(256) __nv_bfloat16 g_xh[(size_t)MROWS * DD];
__device__ __align__(256) __nv_bfloat16 g_xl[(size_t)MROWS * DD];
__device__ __align__(256) __nv_bfloat16 g_wqh[(size_t)3 * DD * DD];
__device__ __align__(256) __nv_bfloat16 g_wql[(size_t)3 * DD * DD];
__device__ __align__(256) __nv_bfloat16 g_wph[(size_t)DD * DD];
__device__ __align__(256) __nv_bfloat16 g_wpl[(size_t)DD * DD];
__device__ __align__(256) __nv_bfloat16 g_yh[(size_t)MROWS * DD];
__device__ __align__(256) __nv_bfloat16 g_yl[(size_t)MROWS * DD];

// ---------------------------------------------------------------------------
// helpers
// ---------------------------------------------------------------------------
__device__ __forceinline__ uint32_t smem_u32(const void* p) {
    uint32_t a;
    asm("{ .reg .u64 t; cvta.to.shared.u64 t, %1; cvt.u32.u64 %0, t; }"
        : "=r"(a) : "l"(p));
    return a;
}
__device__ __forceinline__ void ffma2(u64& d, u64 a, u64 b) {
    asm("fma.rn.f32x2 %0, %1, %2, %0;" : "+l"(d) : "l"(a), "l"(b));
}
__device__ __forceinline__ u64 mul2(u64 a, u64 b) {
    u64 r; asm("mul.rn.f32x2 %0, %1, %2;" : "=l"(r) : "l"(a), "l"(b)); return r;
}
__device__ __forceinline__ u64 pack2(float x, float y) {
    u64 r; asm("mov.b64 %0, {%1, %2};" : "=l"(r) : "f"(x), "f"(y)); return r;
}
__device__ __forceinline__ void unpack2(u64 v, float& x, float& y) {
    asm("mov.b64 {%0, %1}, %2;" : "=f"(x), "=f"(y) : "l"(v));
}
__device__ __forceinline__ void cp16(uint32_t d, const void* g) {
    asm volatile("cp.async.cg.shared.global [%0], [%1], 16;" :: "r"(d), "l"(g));
}

// ---------------------------------------------------------------------------
// fp32 -> bf16 hi/lo split (error-compensated)
// ---------------------------------------------------------------------------
__global__ __launch_bounds__(256) void split_kernel(const float* __restrict__ in,
                                                    __nv_bfloat16* __restrict__ hi,
                                                    __nv_bfloat16* __restrict__ lo,
                                                    int n4) {
    int i = blockIdx.x * blockDim.x + threadIdx.x;
    if (i >= n4) return;
    float4 v = ((const float4*)in)[i];
    __nv_bfloat16 h0 = __float2bfloat16(v.x), h1 = __float2bfloat16(v.y);
    __nv_bfloat16 h2 = __float2bfloat16(v.z), h3 = __float2bfloat16(v.w);
    __nv_bfloat16 l0 = __float2bfloat16(v.x - __bfloat162float(h0));
    __nv_bfloat16 l1 = __float2bfloat16(v.y - __bfloat162float(h1));
    __nv_bfloat16 l2 = __float2bfloat16(v.z - __bfloat162float(h2));
    __nv_bfloat16 l3 = __float2bfloat16(v.w - __bfloat162float(h3));
    ((__nv_bfloat162*)hi)[2 * i]     = __nv_bfloat162(h0, h1);
    ((__nv_bfloat162*)hi)[2 * i + 1] = __nv_bfloat162(h2, h3);
    ((__nv_bfloat162*)lo)[2 * i]     = __nv_bfloat162(l0, l1);
    ((__nv_bfloat162*)lo)[2 * i + 1] = __nv_bfloat162(l2, l3);
}

// ---------------------------------------------------------------------------
// mma.sync bf16x3 GEMM: C[m,n] = sum_k A[m,k]*B[n,k] + bias[n]
// Terms (small->large): Ah*Bl, Al*Bh, Ah*Bh. K=1024 each -> 96 BK=32 stages.
// 128x128 CTA tile, 8 warps (4m x 2n), warp tile 32x64, m16n8k16 HMMA.
// Smem rows 80B pitch: rows 0..7 at fixed 16B chunk hit 8 distinct bank
// groups (0,80,32,112,64,16,96,48 mod 128) -> conflict-free ldmatrix.
// cp.async 3-stage pipeline.
// ---------------------------------------------------------------------------
#define GS 3
#define A_BYTES 10240           // 128 rows * 80B
#define STAGE_B (2 * A_BYTES)   // A + B
#define NIT 96

__device__ __forceinline__ void load_stage(uint32_t sA, uint32_t sB,
                                           const __nv_bfloat16* __restrict__ A,
                                           const __nv_bfloat16* __restrict__ B,
                                           int m0, int n0, int kk, int tid) {
    #pragma unroll
    for (int t = 0; t < 2; t++) {
        const int chunk = tid + t * 256;        // 0..511
        const int row = chunk >> 2;             // 0..127
        const int cc  = chunk & 3;              // 16B chunk in 64B row
        const uint32_t off = row * 80 + cc * 16;
        cp16(sA + off, A + (size_t)(m0 + row) * DD + kk + cc * 8);
        cp16(sB + off, B + (size_t)(n0 + row) * DD + kk + cc * 8);
    }
}

__global__ __launch_bounds__(256, 2)
void mma_gemm_kernel(const __nv_bfloat16* __restrict__ Ah,
                     const __nv_bfloat16* __restrict__ Al,
                     const __nv_bfloat16* __restrict__ Bh,
                     const __nv_bfloat16* __restrict__ Bl,
                     const float* __restrict__ bias,
                     float* __restrict__ C, int ldc) {
    extern __shared__ __align__(1024) char sm[];
    const uint32_t sbase = smem_u32(sm);

    const int tid  = threadIdx.x;
    const int warp = tid >> 5;
    const int lane = tid & 31;
    const int wm = warp >> 1;           // 0..3 -> m offset 32*wm
    const int wn = warp & 1;            // 0..1 -> n offset 64*wn
    const int m0 = blockIdx.y * 128;
    const int n0 = blockIdx.x * 128;

    const __nv_bfloat16* TA[3] = {Ah, Al, Ah};
    const __nv_bfloat16* TB[3] = {Bl, Bh, Bh};

    float acc[2][8][4];
    #pragma unroll
    for (int i = 0; i < 2; i++)
        #pragma unroll
        for (int j = 0; j < 8; j++)
            #pragma unroll
            for (int r = 0; r < 4; r++) acc[i][j][r] = 0.f;

    // prologue: stages for iterations 0 and 1
    #pragma unroll
    for (int s = 0; s < GS - 1; s++) {
        const int term = s >> 5, kk = (s & 31) << 5;
        load_stage(sbase + s * STAGE_B, sbase + s * STAGE_B + A_BYTES,
                   TA[term], TB[term], m0, n0, kk, tid);
        asm volatile("cp.async.commit_group;" ::: "memory");
    }

    // ldmatrix lane addressing: lanes 0-15 -> 16 rows @ chunk cc0,
    // lanes 16-31 -> same rows @ chunk cc0+1 (matrices: r0=(rows0-7,k0-7),
    // r1=(rows8-15,k0-7), r2=(rows0-7,k8-15), r3=(rows8-15,k8-15))
    const int l_sub = lane & 15;        // row within 16
    const int l_cc  = lane >> 4;        // 0/1 -> 16B chunk within k16

    int slot = 0;
    for (int it = 0; it < NIT; it++) {
        asm volatile("cp.async.wait_group %0;" :: "n"(GS - 2) : "memory");
        __syncthreads();

        const int nx = it + GS - 1;
        if (nx < NIT) {
            const int ns = (slot + GS - 1 >= GS) ? (slot + GS - 1 - GS) : (slot + GS - 1);
            const int term = nx >> 5, kk = (nx & 31) << 5;
            load_stage(sbase + ns * STAGE_B, sbase + ns * STAGE_B + A_BYTES,
                       TA[term], TB[term], m0, n0, kk, tid);
        }
        asm volatile("cp.async.commit_group;" ::: "memory");

        const uint32_t sA = sbase + slot * STAGE_B;
        const uint32_t sB = sA + A_BYTES;

        #pragma unroll
        for (int h = 0; h < 2; h++) {       // two k16 halves of BK=32
            const int cc = h * 2 + l_cc;
            uint32_t a[2][4], b[8][2];
            #pragma unroll
            for (int i = 0; i < 2; i++) {
                const int lrow = wm * 32 + i * 16 + l_sub;
                const uint32_t ad = sA + lrow * 80 + cc * 16;
                asm volatile("ldmatrix.sync.aligned.m8n8.x4.shared.b16 {%0,%1,%2,%3}, [%4];"
                    : "=r"(a[i][0]), "=r"(a[i][1]), "=r"(a[i][2]), "=r"(a[i][3]) : "r"(ad));
            }
            #pragma unroll
            for (int j2 = 0; j2 < 4; j2++) {
                const int nrow = wn * 64 + j2 * 16 + l_sub;
                const uint32_t bd = sB + nrow * 80 + cc * 16;
                uint32_t r0, r1, r2, r3;
                asm volatile("ldmatrix.sync.aligned.m8n8.x4.shared.b16 {%0,%1,%2,%3}, [%4];"
                    : "=r"(r0), "=r"(r1), "=r"(r2), "=r"(r3) : "r"(bd));
                // n-block 0 (rows j2*16+0-7): k0-7 = r0, k8-15 = r2
                // n-block 1 (rows j2*16+8-15): k0-7 = r1, k8-15 = r3
                b[j2 * 2][0] = r0;     b[j2 * 2][1] = r2;
                b[j2 * 2 + 1][0] = r1; b[j2 * 2 + 1][1] = r3;
            }
            #pragma unroll
            for (int i = 0; i < 2; i++)
                #pragma unroll
                for (int j = 0; j < 8; j++)
                    asm volatile(
                        "mma.sync.aligned.m16n8k16.row.col.f32.bf16.bf16.f32 "
                        "{%0,%1,%2,%3}, {%4,%5,%6,%7}, {%8,%9}, {%0,%1,%2,%3};"
                        : "+f"(acc[i][j][0]), "+f"(acc[i][j][1]),
                          "+f"(acc[i][j][2]), "+f"(acc[i][j][3])
                        : "r"(a[i][0]), "r"(a[i][1]), "r"(a[i][2]), "r"(a[i][3]),
                          "r"(b[j][0]), "r"(b[j][1]));
        }

        slot = (slot + 1 == GS) ? 0 : slot + 1;
    }

    // epilogue
    const int l4 = lane >> 2;
    const int l2 = (lane & 3) << 1;
    #pragma unroll
    for (int i = 0; i < 2; i++) {
        const int row0 = m0 + wm * 32 + i * 16 + l4;
        #pragma unroll
        for (int j = 0; j < 8; j++) {
            const int col = n0 + wn * 64 + j * 8 + l2;
            const float2 bv = *(const float2*)(bias + col);
            float2 v0, v1;
            v0.x = acc[i][j][0] + bv.x; v0.y = acc[i][j][1] + bv.y;
            v1.x = acc[i][j][2] + bv.x; v1.y = acc[i][j][3] + bv.y;
            *(float2*)(C + (size_t)row0 * ldc + col) = v0;
            *(float2*)(C + (size_t)(row0 + 8) * ldc + col) = v1;
        }
    }
}

// ---------------------------------------------------------------------------
// Flash attention (fp32, causal), FFMA2 pairs along the reduction axis.
// Ks[r][d], Vt[d][c]: 16B-chunk XOR swizzle within each 64-float row.
// ---------------------------------------------------------------------------
#define KIDX(r, d) (((r) << 6) + ((((d) >> 2) ^ ((r) & 15)) << 2) + ((d) & 3))

__global__ __launch_bounds__(256) void flash_attn_kernel() {
    const int qt = blockIdx.x;
    const int h  = blockIdx.y;
    const int b  = blockIdx.z;

    extern __shared__ __align__(16) float smf[];
    float* Qs = smf;               // [64][64] row-major
    float* Ks = smf + 4096;        // swizzled
    float* Vt = smf + 8192;        // transposed + swizzled
    float* Ps = smf + 12288;       // [64][64] row-major (warp-private rows)

    const int tid  = threadIdx.x;
    const int warp = tid >> 5;
    const int lane = tid & 31;
    const int r_base = warp * 8;
    const int q0 = qt * 64;
    const float scale = 0.125f;

    for (int i = tid; i < 64 * 64; i += 256) {
        int r = i >> 6, d = i & 63;
        Qs[(r << 6) + d] = g_qkv[((size_t)(b * TT + q0 + r)) * (3 * DD) + h * HDIM + d] * scale;
    }

    float m[8], l[8];
    u64 o0p[8], o1p[8];
    #pragma unroll
    for (int rr = 0; rr < 8; rr++) { m[rr] = -3.0e38f; l[rr] = 0.f; o0p[rr] = 0ull; o1p[rr] = 0ull; }

    for (int kt = 0; kt <= qt; kt++) {
        const int k0 = kt * 64;
        __syncthreads();
        for (int i = tid; i < 64 * 64; i += 256) {
            int r = i >> 6, d = i & 63;
            size_t base = ((size_t)(b * TT + k0 + r)) * (3 * DD) + h * HDIM + d;
            Ks[KIDX(r, d)] = g_qkv[base + DD];
            Vt[KIDX(d, r)] = g_qkv[base + 2 * DD];
        }
        __syncthreads();

        // ---- S = Q K^T : packed pairs along d ----
        u64 s0p[8], s1p[8];
        #pragma unroll
        for (int rr = 0; rr < 8; rr++) { s0p[rr] = 0ull; s1p[rr] = 0ull; }

        #pragma unroll
        for (int d4 = 0; d4 < 64; d4 += 4) {
            const int coa = (((d4 >> 2) ^ (lane & 15)) << 2);
            const ulonglong2 ka = *(const ulonglong2*)&Ks[(lane << 6) + coa];
            const ulonglong2 kb = *(const ulonglong2*)&Ks[((lane + 32) << 6) + coa];
            #pragma unroll
            for (int rr = 0; rr < 8; rr++) {
                const ulonglong2 qp = *(const ulonglong2*)&Qs[((r_base + rr) << 6) + d4];
                ffma2(s0p[rr], qp.x, ka.x); ffma2(s0p[rr], qp.y, ka.y);
                ffma2(s1p[rr], qp.x, kb.x); ffma2(s1p[rr], qp.y, kb.y);
            }
        }

        // ---- online softmax + stage P ----
        const bool diag = (kt == qt);
        #pragma unroll
        for (int rr = 0; rr < 8; rr++) {
            const int r = r_base + rr;
            float ax, ay, bx, by;
            unpack2(s0p[rr], ax, ay);
            unpack2(s1p[rr], bx, by);
            float v0 = ax + ay, v1 = bx + by;
            if (diag) {
                const int qg = q0 + r;
                if (k0 + lane > qg)      v0 = -3.0e38f;
                if (k0 + lane + 32 > qg) v1 = -3.0e38f;
            }
            float rmax = fmaxf(v0, v1);
            #pragma unroll
            for (int off = 16; off; off >>= 1)
                rmax = fmaxf(rmax, __shfl_xor_sync(0xffffffffu, rmax, off));

            const float mnew = fmaxf(m[rr], rmax);
            const float corr = __expf(m[rr] - mnew);
            const float p0 = __expf(v0 - mnew);
            const float p1 = __expf(v1 - mnew);

            float rs = p0 + p1;
            #pragma unroll
            for (int off = 16; off; off >>= 1)
                rs += __shfl_xor_sync(0xffffffffu, rs, off);

            l[rr] = l[rr] * corr + rs;
            m[rr] = mnew;
            const u64 cc = pack2(corr, corr);
            o0p[rr] = mul2(o0p[rr], cc);
            o1p[rr] = mul2(o1p[rr], cc);
            Ps[(r << 6) + lane]      = p0;
            Ps[(r << 6) + lane + 32] = p1;
        }
        __syncwarp();

        // ---- O += P V : packed pairs along c, V transposed ----
        #pragma unroll
        for (int c4 = 0; c4 < 64; c4 += 4) {
            const int cov = (((c4 >> 2) ^ (lane & 15)) << 2);
            const ulonglong2 va = *(const ulonglong2*)&Vt[(lane << 6) + cov];
            const ulonglong2 vb = *(const ulonglong2*)&Vt[((lane + 32) << 6) + cov];
            #pragma unroll
            for (int rr = 0; rr < 8; rr++) {
                const ulonglong2 pp = *(const ulonglong2*)&Ps[((r_base + rr) << 6) + c4];
                ffma2(o0p[rr], pp.x, va.x); ffma2(o0p[rr], pp.y, va.y);
                ffma2(o1p[rr], pp.x, vb.x); ffma2(o1p[rr], pp.y, vb.y);
            }
        }
    }

    #pragma unroll
    for (int rr = 0; rr < 8; rr++) {
        const int r = r_base + rr;
        const float inv = 1.0f / l[rr];
        float ax, ay, bx, by;
        unpack2(o0p[rr], ax, ay);
        unpack2(o1p[rr], bx, by);
        size_t base = ((size_t)(b * TT + q0 + r)) * DD + h * HDIM;
        g_yatt[base + lane]      = (ax + ay) * inv;
        g_yatt[base + lane + 32] = (bx + by) * inv;
    }
}

// ---------------------------------------------------------------------------
// Host side
// ---------------------------------------------------------------------------
extern "C" void kernel_launch(void* const* d_in, const int* in_sizes, int n_in,
                              void* d_out, int out_size) {
    const float* x      = (const float*)d_in[0];
    const float* w_qkv  = (const float*)d_in[2];
    const float* b_qkv  = (const float*)d_in[3];
    const float* w_proj = (const float*)d_in[4];
    const float* b_proj = (const float*)d_in[5];
    float* out = (float*)d_out;

    void *pxh, *pxl, *pwqh, *pwql, *pwph, *pwpl, *pyh, *pyl, *pqkv, *pyatt;
    cudaGetSymbolAddress(&pxh, g_xh);   cudaGetSymbolAddress(&pxl, g_xl);
    cudaGetSymbolAddress(&pwqh, g_wqh); cudaGetSymbolAddress(&pwql, g_wql);
    cudaGetSymbolAddress(&pwph, g_wph); cudaGetSymbolAddress(&pwpl, g_wpl);
    cudaGetSymbolAddress(&pyh, g_yh);   cudaGetSymbolAddress(&pyl, g_yl);
    cudaGetSymbolAddress(&pqkv, g_qkv); cudaGetSymbolAddress(&pyatt, g_yatt);

    static int attr_set = 0;
    if (!attr_set) {
        cudaFuncSetAttribute(mma_gemm_kernel,
                             cudaFuncAttributeMaxDynamicSharedMemorySize, GS * STAGE_B);
        cudaFuncSetAttribute(flash_attn_kernel,
                             cudaFuncAttributeMaxDynamicSharedMemorySize, 65536);
        attr_set = 1;
    }

    // 1) split inputs to bf16 hi/lo
    split_kernel<<<(MROWS * DD) / 1024, 256>>>(x, (__nv_bfloat16*)pxh, (__nv_bfloat16*)pxl,
                                               (MROWS * DD) / 4);
    split_kernel<<<(3 * DD * DD) / 1024, 256>>>(w_qkv, (__nv_bfloat16*)pwqh, (__nv_bfloat16*)pwql,
                                                (3 * DD * DD) / 4);
    split_kernel<<<(DD * DD) / 1024, 256>>>(w_proj, (__nv_bfloat16*)pwph, (__nv_bfloat16*)pwpl,
                                            (DD * DD) / 4);

    // 2) QKV GEMM: [4096,1024] x [3072,1024]^T -> g_qkv
    {
        dim3 grid((3 * DD) / 128, MROWS / 128);
        mma_gemm_kernel<<<grid, 256, GS * STAGE_B>>>(
            (const __nv_bfloat16*)pxh, (const __nv_bfloat16*)pxl,
            (const __nv_bfloat16*)pwqh, (const __nv_bfloat16*)pwql,
            b_qkv, (float*)pqkv, 3 * DD);
    }

    // 3) flash attention -> g_yatt
    {
        dim3 grid(TT / 64, HH, BB);
        flash_attn_kernel<<<grid, 256, 65536>>>();
    }

    // 4) split attention output to bf16 hi/lo
    split_kernel<<<(MROWS * DD) / 1024, 256>>>((const float*)pyatt, (__nv_bfloat16*)pyh,
                                               (__nv_bfloat16*)pyl, (MROWS * DD) / 4);

    // 5) output projection: [4096,1024] x [1024,1024]^T -> out
    {
        dim3 grid(DD / 128, MROWS / 128);
        mma_gemm_kernel<<<grid, 256, GS * STAGE_B>>>(
            (const __nv_bfloat16*)pyh, (const __nv_bfloat16*)pyl,
            (const __nv_bfloat16*)pwph, (const __nv_bfloat16*)pwpl,
            b_proj, out, DD);
    }
}

// round 7
// speedup vs baseline: 2.1495x; 1.8684x over previous
#include <cuda_runtime.h>
#include <cuda_bf16.h>
#include <cstdint>
#include <math.h>

#define BB 2
#define TT 2048
#define DD 1024
#define HH 16
#define HDIM 64
#define MROWS (BB * TT)   // 4096

// ---------------------------------------------------------------------------
// Scratch (device globals; no allocation anywhere)
// ---------------------------------------------------------------------------
__device__ __align__(256) __nv_bfloat16 g_xh[(size_t)MROWS * DD];
__device__ __align__(256) __nv_bfloat16 g_xl[(size_t)MROWS * DD];
__device__ __align__(256) __nv_bfloat16 g_wqh[(size_t)3 * DD * DD];
__device__ __align__(256) __nv_bfloat16 g_wql[(size_t)3 * DD * DD];
__device__ __align__(256) __nv_bfloat16 g_wph[(size_t)DD * DD];
__device__ __align__(256) __nv_bfloat16 g_wpl[(size_t)DD * DD];
__device__ __align__(256) __nv_bfloat16 g_yh[(size_t)MROWS * DD];
__device__ __align__(256) __nv_bfloat16 g_yl[(size_t)MROWS * DD];
// q/k/v in [b,h,t,d] layout, hi/lo bf16
__device__ __align__(256) __nv_bfloat16 g_qh[(size_t)MROWS * DD];
__device__ __align__(256) __nv_bfloat16 g_ql[(size_t)MROWS * DD];
__device__ __align__(256) __nv_bfloat16 g_kh[(size_t)MROWS * DD];
__device__ __align__(256) __nv_bfloat16 g_kl[(size_t)MROWS * DD];
__device__ __align__(256) __nv_bfloat16 g_vh[(size_t)MROWS * DD];
__device__ __align__(256) __nv_bfloat16 g_vl[(size_t)MROWS * DD];

// ---------------------------------------------------------------------------
// helpers
// ---------------------------------------------------------------------------
__device__ __forceinline__ uint32_t smem_u32(const void* p) {
    uint32_t a;
    asm("{ .reg .u64 t; cvta.to.shared.u64 t, %1; cvt.u32.u64 %0, t; }"
        : "=r"(a) : "l"(p));
    return a;
}
__device__ __forceinline__ void cp16(uint32_t d, const void* g) {
    asm volatile("cp.async.cg.shared.global [%0], [%1], 16;" :: "r"(d), "l"(g));
}
__device__ __forceinline__ void ldsm4(uint32_t* r, uint32_t a) {
    asm volatile("ldmatrix.sync.aligned.m8n8.x4.shared.b16 {%0,%1,%2,%3}, [%4];"
        : "=r"(r[0]), "=r"(r[1]), "=r"(r[2]), "=r"(r[3]) : "r"(a));
}
__device__ __forceinline__ void ldsm4t(uint32_t* r, uint32_t a) {
    asm volatile("ldmatrix.sync.aligned.m8n8.x4.trans.shared.b16 {%0,%1,%2,%3}, [%4];"
        : "=r"(r[0]), "=r"(r[1]), "=r"(r[2]), "=r"(r[3]) : "r"(a));
}
__device__ __forceinline__ void mma16816(float* c, const uint32_t* a, const uint32_t* b) {
    asm volatile("mma.sync.aligned.m16n8k16.row.col.f32.bf16.bf16.f32 "
        "{%0,%1,%2,%3}, {%4,%5,%6,%7}, {%8,%9}, {%0,%1,%2,%3};"
        : "+f"(c[0]), "+f"(c[1]), "+f"(c[2]), "+f"(c[3])
        : "r"(a[0]), "r"(a[1]), "r"(a[2]), "r"(a[3]), "r"(b[0]), "r"(b[1]));
}
// pack two fp32 as bf16x2 {lo -> low half, hi -> high half}
__device__ __forceinline__ uint32_t bfpack(float lo, float hi) {
    uint32_t r;
    asm("cvt.rn.bf16x2.f32 %0, %1, %2;" : "=r"(r) : "f"(hi), "f"(lo));
    return r;
}
// split (v0,v1) into hi bf16x2 and residual-lo bf16x2
__device__ __forceinline__ void split_pack(float v0, float v1, uint32_t& hp, uint32_t& lp) {
    __nv_bfloat16 h0 = __float2bfloat16(v0), h1 = __float2bfloat16(v1);
    hp = ((uint32_t)__bfloat16_as_ushort(h1) << 16) | (uint32_t)__bfloat16_as_ushort(h0);
    lp = bfpack(v0 - __bfloat162float(h0), v1 - __bfloat162float(h1));
}
#define CP_COMMIT() asm volatile("cp.async.commit_group;" ::: "memory")
#define CP_WAIT1()  asm volatile("cp.async.wait_group 1;" ::: "memory")

// ---------------------------------------------------------------------------
// fp32 -> bf16 hi/lo split (inputs)
// ---------------------------------------------------------------------------
__global__ __launch_bounds__(256) void split_kernel(const float* __restrict__ in,
                                                    __nv_bfloat16* __restrict__ hi,
                                                    __nv_bfloat16* __restrict__ lo,
                                                    int n4) {
    int i = blockIdx.x * blockDim.x + threadIdx.x;
    if (i >= n4) return;
    float4 v = ((const float4*)in)[i];
    uint32_t h0, l0, h1, l1;
    split_pack(v.x, v.y, h0, l0);
    split_pack(v.z, v.w, h1, l1);
    ((uint32_t*)hi)[2 * i] = h0; ((uint32_t*)hi)[2 * i + 1] = h1;
    ((uint32_t*)lo)[2 * i] = l0; ((uint32_t*)lo)[2 * i + 1] = l1;
}

// ---------------------------------------------------------------------------
// GEMM mainloop (identical structure to R6-validated kernel)
// acc[i][j][r]: i = m16 block (2), j = n8 tile (8), r = frag reg (4)
// ---------------------------------------------------------------------------
#define GS 3
#define A_BYTES 10240           // 128 rows * 80B
#define STAGE_B (2 * A_BYTES)
#define NIT 96

__device__ __forceinline__ void gemm_load_stage(uint32_t sA, uint32_t sB,
                                                const __nv_bfloat16* __restrict__ A,
                                                const __nv_bfloat16* __restrict__ B,
                                                int m0, int n0, int kk, int tid) {
    #pragma unroll
    for (int t = 0; t < 2; t++) {
        const int chunk = tid + t * 256;
        const int row = chunk >> 2;
        const int cc  = chunk & 3;
        const uint32_t off = row * 80 + cc * 16;
        cp16(sA + off, A + (size_t)(m0 + row) * DD + kk + cc * 8);
        cp16(sB + off, B + (size_t)(n0 + row) * DD + kk + cc * 8);
    }
}

__device__ __forceinline__ void gemm_mainloop(uint32_t sbase,
                                              const __nv_bfloat16* __restrict__ Ah,
                                              const __nv_bfloat16* __restrict__ Al,
                                              const __nv_bfloat16* __restrict__ Bh,
                                              const __nv_bfloat16* __restrict__ Bl,
                                              int m0, int n0, int tid,
                                              float (&acc)[2][8][4]) {
    const int lane = tid & 31;
    const int warp = tid >> 5;
    const int wm = warp >> 1;
    const int wn = warp & 1;

    const __nv_bfloat16* TA[3] = {Ah, Al, Ah};
    const __nv_bfloat16* TB[3] = {Bl, Bh, Bh};

    #pragma unroll
    for (int s = 0; s < GS - 1; s++) {
        const int term = s >> 5, kk = (s & 31) << 5;
        gemm_load_stage(sbase + s * STAGE_B, sbase + s * STAGE_B + A_BYTES,
                        TA[term], TB[term], m0, n0, kk, tid);
        CP_COMMIT();
    }

    const int l_sub = lane & 15;
    const int l_cc  = lane >> 4;

    int slot = 0;
    for (int it = 0; it < NIT; it++) {
        asm volatile("cp.async.wait_group %0;" :: "n"(GS - 2) : "memory");
        __syncthreads();

        const int nx = it + GS - 1;
        if (nx < NIT) {
            const int ns = (slot + GS - 1 >= GS) ? (slot + GS - 1 - GS) : (slot + GS - 1);
            const int term = nx >> 5, kk = (nx & 31) << 5;
            gemm_load_stage(sbase + ns * STAGE_B, sbase + ns * STAGE_B + A_BYTES,
                            TA[term], TB[term], m0, n0, kk, tid);
        }
        CP_COMMIT();

        const uint32_t sA = sbase + slot * STAGE_B;
        const uint32_t sB = sA + A_BYTES;

        #pragma unroll
        for (int h = 0; h < 2; h++) {
            const int cc = h * 2 + l_cc;
            uint32_t a[2][4], b[8][2];
            #pragma unroll
            for (int i = 0; i < 2; i++) {
                const int lrow = wm * 32 + i * 16 + l_sub;
                ldsm4(a[i], sA + lrow * 80 + cc * 16);
            }
            #pragma unroll
            for (int j2 = 0; j2 < 4; j2++) {
                const int nrow = wn * 64 + j2 * 16 + l_sub;
                uint32_t r[4];
                ldsm4(r, sB + nrow * 80 + cc * 16);
                b[j2 * 2][0] = r[0];     b[j2 * 2][1] = r[2];
                b[j2 * 2 + 1][0] = r[1]; b[j2 * 2 + 1][1] = r[3];
            }
            #pragma unroll
            for (int i = 0; i < 2; i++)
                #pragma unroll
                for (int j = 0; j < 8; j++)
                    mma16816(acc[i][j], a[i], b[j]);
        }
        slot = (slot + 1 == GS) ? 0 : slot + 1;
    }
}

// ---- qkv GEMM: scatter epilogue -> q/k/v hi/lo in [b,h,t,d] (q scaled) ----
__global__ __launch_bounds__(256, 2)
void qkv_gemm_kernel(const __nv_bfloat16* __restrict__ Ah,
                     const __nv_bfloat16* __restrict__ Al,
                     const __nv_bfloat16* __restrict__ Bh,
                     const __nv_bfloat16* __restrict__ Bl,
                     const float* __restrict__ bias,
                     __nv_bfloat16* __restrict__ qh, __nv_bfloat16* __restrict__ ql,
                     __nv_bfloat16* __restrict__ kh, __nv_bfloat16* __restrict__ kl,
                     __nv_bfloat16* __restrict__ vh, __nv_bfloat16* __restrict__ vl) {
    extern __shared__ __align__(1024) char sm[];
    const uint32_t sbase = smem_u32(sm);
    const int tid = threadIdx.x;
    const int lane = tid & 31;
    const int warp = tid >> 5;
    const int wm = warp >> 1, wn = warp & 1;
    const int m0 = blockIdx.y * 128;
    const int n0 = blockIdx.x * 128;

    float acc[2][8][4];
    #pragma unroll
    for (int i = 0; i < 2; i++)
        #pragma unroll
        for (int j = 0; j < 8; j++)
            #pragma unroll
            for (int r = 0; r < 4; r++) acc[i][j][r] = 0.f;

    gemm_mainloop(sbase, Ah, Al, Bh, Bl, m0, n0, tid, acc);

    const int l4 = lane >> 2;
    const int l2 = (lane & 3) << 1;
    #pragma unroll
    for (int i = 0; i < 2; i++) {
        const int row = m0 + wm * 32 + i * 16 + l4;   // token index
        const int bi = row >> 11;                     // batch
        const int t  = row & 2047;
        #pragma unroll
        for (int j = 0; j < 8; j++) {
            const int col = n0 + wn * 64 + j * 8 + l2;
            const int type = col >> 10;
            const int hc = (col & 1023) >> 6;
            const int d  = col & 63;
            const float2 bv = *(const float2*)(bias + col);
            float v0 = acc[i][j][0] + bv.x, v1 = acc[i][j][1] + bv.y;
            float v2 = acc[i][j][2] + bv.x, v3 = acc[i][j][3] + bv.y;
            if (type == 0) { v0 *= 0.125f; v1 *= 0.125f; v2 *= 0.125f; v3 *= 0.125f; }
            __nv_bfloat16* dh = (type == 0) ? qh : (type == 1) ? kh : vh;
            __nv_bfloat16* dl = (type == 0) ? ql : (type == 1) ? kl : vl;
            const size_t off0 = (((size_t)(bi * HH + hc)) * TT + t) * 64 + d;
            const size_t off1 = off0 + 8 * 64;        // row+8
            uint32_t hp, lp;
            split_pack(v0, v1, hp, lp);
            ((uint32_t*)dh)[off0 >> 1] = hp; ((uint32_t*)dl)[off0 >> 1] = lp;
            split_pack(v2, v3, hp, lp);
            ((uint32_t*)dh)[off1 >> 1] = hp; ((uint32_t*)dl)[off1 >> 1] = lp;
        }
    }
}

// ---- proj GEMM: fp32 epilogue (same as R6) ----
__global__ __launch_bounds__(256, 2)
void proj_gemm_kernel(const __nv_bfloat16* __restrict__ Ah,
                      const __nv_bfloat16* __restrict__ Al,
                      const __nv_bfloat16* __restrict__ Bh,
                      const __nv_bfloat16* __restrict__ Bl,
                      const float* __restrict__ bias,
                      float* __restrict__ C, int ldc) {
    extern __shared__ __align__(1024) char sm[];
    const uint32_t sbase = smem_u32(sm);
    const int tid = threadIdx.x;
    const int lane = tid & 31;
    const int warp = tid >> 5;
    const int wm = warp >> 1, wn = warp & 1;
    const int m0 = blockIdx.y * 128;
    const int n0 = blockIdx.x * 128;

    float acc[2][8][4];
    #pragma unroll
    for (int i = 0; i < 2; i++)
        #pragma unroll
        for (int j = 0; j < 8; j++)
            #pragma unroll
            for (int r = 0; r < 4; r++) acc[i][j][r] = 0.f;

    gemm_mainloop(sbase, Ah, Al, Bh, Bl, m0, n0, tid, acc);

    const int l4 = lane >> 2;
    const int l2 = (lane & 3) << 1;
    #pragma unroll
    for (int i = 0; i < 2; i++) {
        const int row0 = m0 + wm * 32 + i * 16 + l4;
        #pragma unroll
        for (int j = 0; j < 8; j++) {
            const int col = n0 + wn * 64 + j * 8 + l2;
            const float2 bv = *(const float2*)(bias + col);
            float2 v0, v1;
            v0.x = acc[i][j][0] + bv.x; v0.y = acc[i][j][1] + bv.y;
            v1.x = acc[i][j][2] + bv.x; v1.y = acc[i][j][3] + bv.y;
            *(float2*)(C + (size_t)row0 * ldc + col) = v0;
            *(float2*)(C + (size_t)(row0 + 8) * ldc + col) = v1;
        }
    }
}

// ---------------------------------------------------------------------------
// Flash attention on mma.sync (bf16x3). CTA = 128 q rows x (head, batch).
// 8 warps, warp = m16 rows. kv tiles of 64, cp.async double buffer.
// smem: Qh[128x144B] Ql[128x144B] | 2 stages x {Kh,Kl,Vh,Vl}[64x144B each]
// ---------------------------------------------------------------------------
#define AP 144
#define Q_BYTES (128 * AP)          // 18432
#define KV_TILE_B (64 * AP)         // 9216
#define KV_STAGE_B (4 * KV_TILE_B)  // 36864
#define ATT_SMEM (2 * Q_BYTES + 2 * KV_STAGE_B)  // 110592

__global__ __launch_bounds__(256, 1)
void attn_mma_kernel(const __nv_bfloat16* __restrict__ qh, const __nv_bfloat16* __restrict__ ql,
                     const __nv_bfloat16* __restrict__ kh, const __nv_bfloat16* __restrict__ kl,
                     const __nv_bfloat16* __restrict__ vh, const __nv_bfloat16* __restrict__ vl,
                     __nv_bfloat16* __restrict__ yh, __nv_bfloat16* __restrict__ yl) {
    extern __shared__ __align__(1024) char sm[];
    const uint32_t sb = smem_u32(sm);

    const int qi = blockIdx.x;           // 0..15
    const int h  = blockIdx.y;           // 0..15
    const int b  = blockIdx.z;           // 0..1
    const int q0 = qi * 128;
    const size_t base = ((size_t)(b * HH + h)) * TT * 64;

    const int tid  = threadIdx.x;
    const int warp = tid >> 5;
    const int lane = tid & 31;
    const int l_sub = lane & 15;
    const int l_cc  = lane >> 4;
    const int lq = lane >> 2;            // acc row within 8
    const int lr = lane & 3;             // acc col quad

    // ---- prologue: stage Q (group 0) and kv stage 0 (group 1) ----
    #pragma unroll
    for (int t2 = 0; t2 < 4; t2++) {
        const int idx = tid + t2 * 256;  // 0..1023
        const int row = idx >> 3, ch = idx & 7;
        const uint32_t off = row * AP + ch * 16;
        const size_t g = base + (size_t)(q0 + row) * 64 + ch * 8;
        cp16(sb + off, qh + g);
        cp16(sb + Q_BYTES + off, ql + g);
    }
    CP_COMMIT();

    const int nt = 2 * qi + 2;
    auto load_kv = [&](int s, int k0) {
        const uint32_t st = sb + 2 * Q_BYTES + s * KV_STAGE_B;
        const size_t srcb = base + (size_t)k0 * 64;
        #pragma unroll
        for (int t2 = 0; t2 < 2; t2++) {
            const int idx = tid + t2 * 256;  // 0..511
            const int row = idx >> 3, ch = idx & 7;
            const uint32_t off = row * AP + ch * 16;
            const size_t g = srcb + (size_t)row * 64 + ch * 8;
            cp16(st + off, kh + g);
            cp16(st + KV_TILE_B + off, kl + g);
            cp16(st + 2 * KV_TILE_B + off, vh + g);
            cp16(st + 3 * KV_TILE_B + off, vl + g);
        }
    };
    load_kv(0, 0);
    CP_COMMIT();

    CP_WAIT1();          // Q group done (stage0 may still fly)
    __syncthreads();

    // ---- Q fragments (kept in registers) ----
    uint32_t aqh[4][4], aql[4][4];
    #pragma unroll
    for (int kk = 0; kk < 4; kk++) {
        const uint32_t off = (warp * 16 + l_sub) * AP + (kk * 2 + l_cc) * 16;
        ldsm4(aqh[kk], sb + off);
        ldsm4(aql[kk], sb + Q_BYTES + off);
    }

    float m0r = -1e30f, m1r = -1e30f, l0 = 0.f, l1 = 0.f;
    float o[8][4];
    #pragma unroll
    for (int j = 0; j < 8; j++)
        #pragma unroll
        for (int r = 0; r < 4; r++) o[j][r] = 0.f;

    const int r0g = q0 + warp * 16 + lq;
    const int r1g = r0g + 8;
    const int rowmaxw = q0 + warp * 16 + 15;

    for (int kt = 0; kt < nt; kt++) {
        const int k0 = kt * 64;
        if (kt + 1 < nt) load_kv((kt + 1) & 1, (kt + 1) * 64);
        CP_COMMIT();
        CP_WAIT1();
        __syncthreads();

        if (k0 <= rowmaxw) {   // warp not fully above the diagonal
            const uint32_t st = sb + 2 * Q_BYTES + (kt & 1) * KV_STAGE_B;

            // ---- S = Q K^T (3 terms) ----
            float s[8][4];
            #pragma unroll
            for (int j = 0; j < 8; j++)
                #pragma unroll
                for (int r = 0; r < 4; r++) s[j][r] = 0.f;

            #pragma unroll
            for (int kk = 0; kk < 4; kk++) {
                uint32_t bk[8][2];
                #pragma unroll
                for (int j2 = 0; j2 < 4; j2++) {
                    uint32_t r[4];
                    ldsm4(r, st + (j2 * 16 + l_sub) * AP + (kk * 2 + l_cc) * 16);
                    bk[j2 * 2][0] = r[0];     bk[j2 * 2][1] = r[2];
                    bk[j2 * 2 + 1][0] = r[1]; bk[j2 * 2 + 1][1] = r[3];
                }
                #pragma unroll
                for (int j = 0; j < 8; j++) mma16816(s[j], aqh[kk], bk[j]);
                #pragma unroll
                for (int j = 0; j < 8; j++) mma16816(s[j], aql[kk], bk[j]);
                #pragma unroll
                for (int j2 = 0; j2 < 4; j2++) {
                    uint32_t r[4];
                    ldsm4(r, st + KV_TILE_B + (j2 * 16 + l_sub) * AP + (kk * 2 + l_cc) * 16);
                    bk[j2 * 2][0] = r[0];     bk[j2 * 2][1] = r[2];
                    bk[j2 * 2 + 1][0] = r[1]; bk[j2 * 2 + 1][1] = r[3];
                }
                #pragma unroll
                for (int j = 0; j < 8; j++) mma16816(s[j], aqh[kk], bk[j]);
            }

            // ---- causal mask (diagonal tiles only) ----
            if (k0 + 63 > q0 + warp * 16) {
                #pragma unroll
                for (int j = 0; j < 8; j++) {
                    const int c = k0 + 8 * j + 2 * lr;
                    if (c > r0g)     s[j][0] = -1e30f;
                    if (c + 1 > r0g) s[j][1] = -1e30f;
                    if (c > r1g)     s[j][2] = -1e30f;
                    if (c + 1 > r1g) s[j][3] = -1e30f;
                }
            }

            // ---- online softmax (register-resident) ----
            float mx0 = -1e30f, mx1 = -1e30f;
            #pragma unroll
            for (int j = 0; j < 8; j++) {
                mx0 = fmaxf(mx0, fmaxf(s[j][0], s[j][1]));
                mx1 = fmaxf(mx1, fmaxf(s[j][2], s[j][3]));
            }
            #pragma unroll
            for (int off = 1; off <= 2; off <<= 1) {
                mx0 = fmaxf(mx0, __shfl_xor_sync(0xffffffffu, mx0, off));
                mx1 = fmaxf(mx1, __shfl_xor_sync(0xffffffffu, mx1, off));
            }
            const float mn0 = fmaxf(m0r, mx0), mn1 = fmaxf(m1r, mx1);
            const float c0 = __expf(m0r - mn0), c1 = __expf(m1r - mn1);
            m0r = mn0; m1r = mn1;

            float rs0 = 0.f, rs1 = 0.f;
            #pragma unroll
            for (int j = 0; j < 8; j++) {
                s[j][0] = __expf(s[j][0] - mn0);
                s[j][1] = __expf(s[j][1] - mn0);
                s[j][2] = __expf(s[j][2] - mn1);
                s[j][3] = __expf(s[j][3] - mn1);
                rs0 += s[j][0] + s[j][1];
                rs1 += s[j][2] + s[j][3];
            }
            #pragma unroll
            for (int off = 1; off <= 2; off <<= 1) {
                rs0 += __shfl_xor_sync(0xffffffffu, rs0, off);
                rs1 += __shfl_xor_sync(0xffffffffu, rs1, off);
            }
            l0 = l0 * c0 + rs0;
            l1 = l1 * c1 + rs1;
            #pragma unroll
            for (int j = 0; j < 8; j++) {
                o[j][0] *= c0; o[j][1] *= c0;
                o[j][2] *= c1; o[j][3] *= c1;
            }

            // ---- O += P V (3 terms), P -> A frags straight from acc ----
            #pragma unroll
            for (int kg = 0; kg < 4; kg++) {
                uint32_t ah[4], al[4];
                split_pack(s[2 * kg][0], s[2 * kg][1], ah[0], al[0]);
                split_pack(s[2 * kg][2], s[2 * kg][3], ah[1], al[1]);
                split_pack(s[2 * kg + 1][0], s[2 * kg + 1][1], ah[2], al[2]);
                split_pack(s[2 * kg + 1][2], s[2 * kg + 1][3], ah[3], al[3]);

                const int mm = lane >> 3;
                const int rowv = kg * 16 + (mm & 1) * 8 + (lane & 7);
                const int chb = mm >> 1;

                uint32_t bv[8][2];
                #pragma unroll
                for (int dg = 0; dg < 4; dg++) {
                    uint32_t r[4];
                    ldsm4t(r, st + 2 * KV_TILE_B + rowv * AP + (dg * 2 + chb) * 16);
                    bv[dg * 2][0] = r[0];     bv[dg * 2][1] = r[1];
                    bv[dg * 2 + 1][0] = r[2]; bv[dg * 2 + 1][1] = r[3];
                }
                #pragma unroll
                for (int jn = 0; jn < 8; jn++) mma16816(o[jn], ah, bv[jn]);
                #pragma unroll
                for (int jn = 0; jn < 8; jn++) mma16816(o[jn], al, bv[jn]);
                #pragma unroll
                for (int dg = 0; dg < 4; dg++) {
                    uint32_t r[4];
                    ldsm4t(r, st + 3 * KV_TILE_B + rowv * AP + (dg * 2 + chb) * 16);
                    bv[dg * 2][0] = r[0];     bv[dg * 2][1] = r[1];
                    bv[dg * 2 + 1][0] = r[2]; bv[dg * 2 + 1][1] = r[3];
                }
                #pragma unroll
                for (int jn = 0; jn < 8; jn++) mma16816(o[jn], ah, bv[jn]);
            }
        }
        __syncthreads();
    }

    // ---- epilogue: normalize, split to bf16 hi/lo, write y [token][D] ----
    const float inv0 = 1.0f / l0;
    const float inv1 = 1.0f / l1;
    const size_t tok0 = (size_t)(b * TT + q0 + warp * 16 + lq);
    const size_t tok1 = tok0 + 8;
    #pragma unroll
    for (int jn = 0; jn < 8; jn++) {
        const int d = 8 * jn + 2 * lr;
        uint32_t hp, lp;
        split_pack(o[jn][0] * inv0, o[jn][1] * inv0, hp, lp);
        const size_t off0 = (tok0 * DD + h * 64 + d) >> 1;
        ((uint32_t*)yh)[off0] = hp; ((uint32_t*)yl)[off0] = lp;
        split_pack(o[jn][2] * inv1, o[jn][3] * inv1, hp, lp);
        const size_t off1 = (tok1 * DD + h * 64 + d) >> 1;
        ((uint32_t*)yh)[off1] = hp; ((uint32_t*)yl)[off1] = lp;
    }
}

// ---------------------------------------------------------------------------
// Host side
// ---------------------------------------------------------------------------
extern "C" void kernel_launch(void* const* d_in, const int* in_sizes, int n_in,
                              void* d_out, int out_size) {
    const float* x      = (const float*)d_in[0];
    const float* w_qkv  = (const float*)d_in[2];
    const float* b_qkv  = (const float*)d_in[3];
    const float* w_proj = (const float*)d_in[4];
    const float* b_proj = (const float*)d_in[5];
    float* out = (float*)d_out;

    void *pxh, *pxl, *pwqh, *pwql, *pwph, *pwpl, *pyh, *pyl;
    void *pqh, *pql, *pkh, *pkl, *pvh, *pvl;
    cudaGetSymbolAddress(&pxh, g_xh);   cudaGetSymbolAddress(&pxl, g_xl);
    cudaGetSymbolAddress(&pwqh, g_wqh); cudaGetSymbolAddress(&pwql, g_wql);
    cudaGetSymbolAddress(&pwph, g_wph); cudaGetSymbolAddress(&pwpl, g_wpl);
    cudaGetSymbolAddress(&pyh, g_yh);   cudaGetSymbolAddress(&pyl, g_yl);
    cudaGetSymbolAddress(&pqh, g_qh);   cudaGetSymbolAddress(&pql, g_ql);
    cudaGetSymbolAddress(&pkh, g_kh);   cudaGetSymbolAddress(&pkl, g_kl);
    cudaGetSymbolAddress(&pvh, g_vh);   cudaGetSymbolAddress(&pvl, g_vl);

    static int attr_set = 0;
    if (!attr_set) {
        cudaFuncSetAttribute(qkv_gemm_kernel,
                             cudaFuncAttributeMaxDynamicSharedMemorySize, GS * STAGE_B);
        cudaFuncSetAttribute(proj_gemm_kernel,
                             cudaFuncAttributeMaxDynamicSharedMemorySize, GS * STAGE_B);
        cudaFuncSetAttribute(attn_mma_kernel,
                             cudaFuncAttributeMaxDynamicSharedMemorySize, ATT_SMEM);
        attr_set = 1;
    }

    // 1) split inputs to bf16 hi/lo
    split_kernel<<<(MROWS * DD) / 1024, 256>>>(x, (__nv_bfloat16*)pxh, (__nv_bfloat16*)pxl,
                                               (MROWS * DD) / 4);
    split_kernel<<<(3 * DD * DD) / 1024, 256>>>(w_qkv, (__nv_bfloat16*)pwqh, (__nv_bfloat16*)pwql,
                                                (3 * DD * DD) / 4);
    split_kernel<<<(DD * DD) / 1024, 256>>>(w_proj, (__nv_bfloat16*)pwph, (__nv_bfloat16*)pwpl,
                                            (DD * DD) / 4);

    // 2) QKV GEMM -> q/k/v hi/lo in [b,h,t,d] (q pre-scaled by 1/8)
    {
        dim3 grid((3 * DD) / 128, MROWS / 128);
        qkv_gemm_kernel<<<grid, 256, GS * STAGE_B>>>(
            (const __nv_bfloat16*)pxh, (const __nv_bfloat16*)pxl,
            (const __nv_bfloat16*)pwqh, (const __nv_bfloat16*)pwql,
            b_qkv,
            (__nv_bfloat16*)pqh, (__nv_bfloat16*)pql,
            (__nv_bfloat16*)pkh, (__nv_bfloat16*)pkl,
            (__nv_bfloat16*)pvh, (__nv_bfloat16*)pvl);
    }

    // 3) flash attention (mma.sync) -> y hi/lo
    {
        dim3 grid(TT / 128, HH, BB);
        attn_mma_kernel<<<grid, 256, ATT_SMEM>>>(
            (const __nv_bfloat16*)pqh, (const __nv_bfloat16*)pql,
            (const __nv_bfloat16*)pkh, (const __nv_bfloat16*)pkl,
            (const __nv_bfloat16*)pvh, (const __nv_bfloat16*)pvl,
            (__nv_bfloat16*)pyh, (__nv_bfloat16*)pyl);
    }

    // 4) output projection -> out (fp32)
    {
        dim3 grid(DD / 128, MROWS / 128);
        proj_gemm_kernel<<<grid, 256, GS * STAGE_B>>>(
            (const __nv_bfloat16*)pyh, (const __nv_bfloat16*)pyl,
            (const __nv_bfloat16*)pwph, (const __nv_bfloat16*)pwpl,
            b_proj, out, DD);
    }
}